// round 11
// baseline (speedup 1.0000x reference)
#include <cuda_runtime.h>
#include <cuda_bf16.h>
#include <math.h>
#include <stdint.h>

#define BATCH    64
#define IN_SIZE  1024
#define IN_DIM   256
#define HEADS    4
#define OUT_SIZE 64
#define OUT_DIM  256
#define NMAT     (BATCH * HEADS)     /* 256 */
#define HID      (HEADS * IN_DIM)    /* 1024 */
#define MAX_ITER 10

// ---------------------------------------------------------------------------
// Scratch
// ---------------------------------------------------------------------------
__device__ float g_K[(size_t)NMAT * IN_SIZE * OUT_SIZE];        // 64 MB [n][s][o]
__device__ float g_v[(size_t)NMAT * OUT_SIZE];
__device__ __nv_bfloat16 g_xT_hi[(size_t)BATCH * IN_DIM * IN_SIZE];   // [b][d][s]
__device__ __nv_bfloat16 g_xT_lo[(size_t)BATCH * IN_DIM * IN_SIZE];
__device__ __nv_bfloat16 g_kT_hi[(size_t)NMAT * OUT_SIZE * IN_SIZE];  // [n][o][s]
__device__ __nv_bfloat16 g_kT_lo[(size_t)NMAT * OUT_SIZE * IN_SIZE];
__device__ __nv_bfloat16 g_att_hi[(size_t)BATCH * OUT_SIZE * HID];    // [m][k]
__device__ __nv_bfloat16 g_att_lo[(size_t)BATCH * OUT_SIZE * HID];
__device__ __nv_bfloat16 g_lw_hi[(size_t)OUT_DIM * HID];              // [nn][k]
__device__ __nv_bfloat16 g_lw_lo[(size_t)OUT_DIM * HID];
__device__ __nv_bfloat16 g_w_hi[(size_t)HEADS * OUT_SIZE * IN_DIM];   // [ho][d]
__device__ __nv_bfloat16 g_w_lo[(size_t)HEADS * OUT_SIZE * IN_DIM];

// ---------------------------------------------------------------------------
// Helpers (base-target PTX only)
// ---------------------------------------------------------------------------
__device__ __forceinline__ uint32_t smem_u32(const void* p) {
    uint32_t a;
    asm("{ .reg .u64 t; cvta.to.shared.u64 t, %1; cvt.u32.u64 %0, t; }" : "=r"(a) : "l"(p));
    return a;
}
__device__ __forceinline__ void ldsm4(uint32_t* r, uint32_t a) {
    asm volatile("ldmatrix.sync.aligned.m8n8.x4.shared.b16 {%0,%1,%2,%3}, [%4];"
        : "=r"(r[0]), "=r"(r[1]), "=r"(r[2]), "=r"(r[3]) : "r"(a));
}
__device__ __forceinline__ void ldsm2(uint32_t* r, uint32_t a) {
    asm volatile("ldmatrix.sync.aligned.m8n8.x2.shared.b16 {%0,%1}, [%2];"
        : "=r"(r[0]), "=r"(r[1]) : "r"(a));
}
__device__ __forceinline__ void mma16816(float* c, const uint32_t* a, const uint32_t* b) {
    asm volatile(
        "mma.sync.aligned.m16n8k16.row.col.f32.bf16.bf16.f32 "
        "{%0,%1,%2,%3}, {%4,%5,%6,%7}, {%8,%9}, {%0,%1,%2,%3};"
        : "+f"(c[0]), "+f"(c[1]), "+f"(c[2]), "+f"(c[3])
        : "r"(a[0]), "r"(a[1]), "r"(a[2]), "r"(a[3]), "r"(b[0]), "r"(b[1]));
}
__device__ __forceinline__ uint32_t pack2(__nv_bfloat16 a, __nv_bfloat16 b) {
    uint16_t ua = *(uint16_t*)&a, ub = *(uint16_t*)&b;
    return (uint32_t)ua | ((uint32_t)ub << 16);
}
__device__ __forceinline__ void split2(float f, __nv_bfloat16& h, __nv_bfloat16& l) {
    h = __float2bfloat16(f);
    l = __float2bfloat16(f - __bfloat162float(h));
}

#define RS 72
// Small-tile layout (linear_mma, 256 threads): A 128 rows, B 64 rows
#define OFF_AH 0
#define OFF_AL (128 * RS * 2)
#define OFF_BH (2 * 128 * RS * 2)
#define OFF_BL (2 * 128 * RS * 2 + 64 * RS * 2)
#define DSMEM_BYTES (2 * 128 * RS * 2 + 2 * 64 * RS * 2)   /* 55296 */

// Big-tile layout (gemm_k/attn, 512 threads): A 128 rows, B 256 rows
#define A2_BYTES (128 * RS * 2)   /* 18432 */
#define B2_BYTES (256 * RS * 2)   /* 36864 */
#define OFF2_AH 0
#define OFF2_AL A2_BYTES
#define OFF2_BH (2 * A2_BYTES)
#define OFF2_BL (2 * A2_BYTES + B2_BYTES)
#define DSMEM2 (2 * A2_BYTES + 2 * B2_BYTES)   /* 110592 */

// Sinkhorn SMEM-K stride
#define KST 67
#define SINK_BYTES (512 * KST * 4)    /* 137216 */

// ---------------------------------------------------------------------------
// Kernel 0a: W fp32 [4*64][256] -> bf16 hi/lo
// ---------------------------------------------------------------------------
__global__ __launch_bounds__(256) void wsplit_kernel(const float* __restrict__ W) {
    int i = blockIdx.x * 256 + threadIdx.x;
    float4 v = *(const float4*)(W + (size_t)i * 4);
    __nv_bfloat16 h0, h1, h2, h3, l0, l1, l2, l3;
    split2(v.x, h0, l0); split2(v.y, h1, l1);
    split2(v.z, h2, l2); split2(v.w, h3, l3);
    *(uint2*)(g_w_hi + (size_t)i * 4) = make_uint2(pack2(h0, h1), pack2(h2, h3));
    *(uint2*)(g_w_lo + (size_t)i * 4) = make_uint2(pack2(l0, l1), pack2(l2, l3));
}

// ---------------------------------------------------------------------------
// Kernel 0b: lin_w fp32 -> bf16 hi/lo
// ---------------------------------------------------------------------------
__global__ __launch_bounds__(256) void lwsplit_kernel(const float* __restrict__ lw) {
    int i = blockIdx.x * 256 + threadIdx.x;
    float4 v = *(const float4*)(lw + (size_t)i * 4);
    __nv_bfloat16 h0, h1, h2, h3, l0, l1, l2, l3;
    split2(v.x, h0, l0); split2(v.y, h1, l1);
    split2(v.z, h2, l2); split2(v.w, h3, l3);
    *(uint2*)(g_lw_hi + (size_t)i * 4) = make_uint2(pack2(h0, h1), pack2(h2, h3));
    *(uint2*)(g_lw_lo + (size_t)i * 4) = make_uint2(pack2(l0, l1), pack2(l2, l3));
}

// ---------------------------------------------------------------------------
// Kernel 1: K = exp(10 * x·Wᵀ), head-batched: CTA = (s-tile 128, b).
// M=128(s) N=256(h,o) K=256(d), 4 chunks of 64. 512 threads = 4x4 warps,
// warp tile 32x64 (2 f x 8 g frags).
// ---------------------------------------------------------------------------
__global__ __launch_bounds__(512, 1) void gemm_k_mma(const float* __restrict__ x) {
    extern __shared__ char dyn[];
    __nv_bfloat16* Ah = (__nv_bfloat16*)(dyn + OFF2_AH);
    __nv_bfloat16* Al = (__nv_bfloat16*)(dyn + OFF2_AL);
    __nv_bfloat16* Bh = (__nv_bfloat16*)(dyn + OFF2_BH);
    __nv_bfloat16* Bl = (__nv_bfloat16*)(dyn + OFF2_BL);

    int tid = threadIdx.x, lane = tid & 31, wid = tid >> 5;
    int wm = wid & 3, wn = wid >> 2;
    int b = blockIdx.y;
    int s0 = blockIdx.x * 128;
    const float* xg = x + ((size_t)b * IN_SIZE + s0) * IN_DIM;

    uint32_t aBaseH = smem_u32(Ah) + ((wm * 32 + (lane & 15)) * RS + (lane >> 4) * 8) * 2;
    uint32_t aBaseL = aBaseH + A2_BYTES;
    uint32_t bBaseH = smem_u32(Bh) + ((wn * 64 + (lane & 15)) * RS + (lane >> 4) * 8) * 2;
    uint32_t bBaseL = bBaseH + B2_BYTES;

    float c[2][8][4];
    #pragma unroll
    for (int f = 0; f < 2; ++f)
        #pragma unroll
        for (int g = 0; g < 8; ++g)
            #pragma unroll
            for (int q = 0; q < 4; ++q) c[f][g][q] = 0.f;

    for (int ch = 0; ch < 4; ++ch) {
        int d0 = ch * 64;
        // A: 128 x 64 fp32 -> hi/lo split (once per (b, s-tile): heads batched)
        #pragma unroll
        for (int i = 0; i < 4; ++i) {
            int vi = i * 512 + tid;
            int row = vi >> 4, c4 = (vi & 15) * 4;
            float4 v = *(const float4*)(xg + (size_t)row * IN_DIM + d0 + c4);
            __nv_bfloat16 h0, h1, h2, h3, l0, l1, l2, l3;
            split2(v.x, h0, l0); split2(v.y, h1, l1);
            split2(v.z, h2, l2); split2(v.w, h3, l3);
            int off = row * RS + c4;
            *(uint2*)(Ah + off) = make_uint2(pack2(h0, h1), pack2(h2, h3));
            *(uint2*)(Al + off) = make_uint2(pack2(l0, l1), pack2(l2, l3));
        }
        // B: 256 x 64 bf16 copies from pre-split W
        #pragma unroll
        for (int i = 0; i < 4; ++i) {
            int vi = i * 512 + tid;
            int row = vi >> 3, cu = vi & 7;
            size_t goff = (size_t)row * IN_DIM + d0 + cu * 8;
            int off = row * RS + cu * 8;
            *(uint4*)(Bh + off) = *(const uint4*)(g_w_hi + goff);
            *(uint4*)(Bl + off) = *(const uint4*)(g_w_lo + goff);
        }
        __syncthreads();
        #pragma unroll
        for (int ks = 0; ks < 4; ++ks) {
            uint32_t ah[2][4], al[2][4];
            #pragma unroll
            for (int f = 0; f < 2; ++f) {
                uint32_t o = (uint32_t)(f * 16 * RS + ks * 16) * 2;
                ldsm4(ah[f], aBaseH + o);
                ldsm4(al[f], aBaseL + o);
            }
            #pragma unroll
            for (int gp = 0; gp < 4; ++gp) {
                uint32_t rh[4], rl[4];
                uint32_t o = (uint32_t)(gp * 16 * RS + ks * 16) * 2;
                ldsm4(rh, bBaseH + o);
                ldsm4(rl, bBaseL + o);
                uint32_t bh0[2] = {rh[0], rh[2]}, bh1[2] = {rh[1], rh[3]};
                uint32_t bl0[2] = {rl[0], rl[2]}, bl1[2] = {rl[1], rl[3]};
                #pragma unroll
                for (int f = 0; f < 2; ++f) {
                    mma16816(c[f][2 * gp],     ah[f], bh0);
                    mma16816(c[f][2 * gp],     ah[f], bl0);
                    mma16816(c[f][2 * gp],     al[f], bh0);
                    mma16816(c[f][2 * gp + 1], ah[f], bh1);
                    mma16816(c[f][2 * gp + 1], ah[f], bl1);
                    mma16816(c[f][2 * gp + 1], al[f], bh1);
                }
            }
        }
        __syncthreads();
    }

    // Epilogue: exp(10*acc) -> g_K[(b*4+h)][s][o], col = h*64+o
    #pragma unroll
    for (int f = 0; f < 2; ++f) {
        int s = s0 + wm * 32 + f * 16 + (lane >> 2);
        #pragma unroll
        for (int g = 0; g < 8; ++g) {
            int col = wn * 64 + g * 8 + (lane & 3) * 2;
            int h = col >> 6, o = col & 63;
            float* p0 = g_K + (((size_t)(b * 4 + h)) * IN_SIZE + s) * OUT_SIZE + o;
            float* p1 = p0 + 8 * OUT_SIZE;
            *(float2*)p0 = make_float2(expf(c[f][g][0] * 10.f), expf(c[f][g][1] * 10.f));
            *(float2*)p1 = make_float2(expf(c[f][g][2] * 10.f), expf(c[f][g][3] * 10.f));
        }
    }
}

// ---------------------------------------------------------------------------
// Kernel 2: x[b][s][d] fp32 -> g_xT_hi/lo[b][d][s] bf16
// ---------------------------------------------------------------------------
__global__ __launch_bounds__(256) void xsplit_kernel(const float* __restrict__ x) {
    __shared__ float sm[64][65];
    int tid = threadIdx.x;
    int s0 = blockIdx.x * 64, d0 = blockIdx.y * 64, b = blockIdx.z;
    const float* xb = x + ((size_t)b * IN_SIZE + s0) * IN_DIM + d0;
    #pragma unroll
    for (int i = 0; i < 4; ++i) {
        int vi = i * 256 + tid;
        int rs = vi >> 4, c4 = (vi & 15) * 4;
        float4 v = *(const float4*)(xb + (size_t)rs * IN_DIM + c4);
        sm[rs][c4] = v.x; sm[rs][c4 + 1] = v.y; sm[rs][c4 + 2] = v.z; sm[rs][c4 + 3] = v.w;
    }
    __syncthreads();
    #pragma unroll
    for (int i = 0; i < 4; ++i) {
        int vi = i * 256 + tid;
        int rd = vi >> 4, s4 = (vi & 15) * 4;
        __nv_bfloat16 h[4], l[4];
        #pragma unroll
        for (int j = 0; j < 4; ++j) split2(sm[s4 + j][rd], h[j], l[j]);
        size_t off = ((size_t)b * IN_DIM + d0 + rd) * IN_SIZE + s0 + s4;
        *(uint2*)(g_xT_hi + off) = make_uint2(pack2(h[0], h[1]), pack2(h[2], h[3]));
        *(uint2*)(g_xT_lo + off) = make_uint2(pack2(l[0], l[1]), pack2(l[2], l[3]));
    }
}

// ---------------------------------------------------------------------------
// Kernel 3: Sinkhorn fused (identical to R10 known-good version)
// ---------------------------------------------------------------------------
__global__ void __cluster_dims__(2, 1, 1) __launch_bounds__(1024, 1)
sinkhorn_fused(const int* __restrict__ mask) {
    extern __shared__ float sK[];
    __shared__ float sm_mask[512];
    __shared__ float sm_v[OUT_SIZE];
    __shared__ float sm_u[512];
    __shared__ float sm_ph[2][512];
    __shared__ float sm_vacc[16][OUT_SIZE];
    __shared__ float sm_exch[2][OUT_SIZE];
    __shared__ float sm_red[32];
    __shared__ float sm_a;

    int tid = threadIdx.x, lane = tid & 31, wid = tid >> 5;
    uint32_t rank;
    asm("mov.u32 %0, %%cluster_ctarank;" : "=r"(rank));
    int n = blockIdx.x >> 1;
    int b = n >> 2;
    int srow0 = (int)rank * 512;

    const int* mb = mask + (size_t)b * IN_SIZE;
    float m = (mb[tid] != 0) ? 1.f : 0.f;
    if ((uint32_t)(tid >> 9) == rank) sm_mask[tid & 511] = m;
    float s = m;
    #pragma unroll
    for (int off = 16; off; off >>= 1) s += __shfl_xor_sync(0xffffffffu, s, off);
    if (lane == 0) sm_red[wid] = s;
    if (tid < OUT_SIZE) sm_v[tid] = 1.0f;
    __syncthreads();
    if (tid == 0) {
        float t = 0.f;
        #pragma unroll
        for (int w = 0; w < 32; ++w) t += sm_red[w];
        sm_a = (float)OUT_SIZE / t;
    }

    {
        const float4* g4 = (const float4*)(g_K + ((size_t)n * IN_SIZE + srow0) * OUT_SIZE);
        #pragma unroll
        for (int i = 0; i < 8; ++i) {
            int idx = i * 1024 + tid;
            int row = idx >> 4, q = idx & 15;
            float4 v = g4[idx];
            float* d = sK + row * KST + q * 4;
            d[0] = v.x; d[1] = v.y; d[2] = v.z; d[3] = v.w;
        }
    }
    __syncthreads();
    float a = sm_a;

    int half = tid >> 9;
    int r = tid & 511;
    int o = tid & 63, rg = tid >> 6;

    for (int it = 0; it < MAX_ITER; ++it) {
        {
            const float* kr = sK + r * KST + half * 32;
            const float* vv = sm_v + half * 32;
            float p0 = 0.f, p1 = 0.f;
            #pragma unroll
            for (int j = 0; j < 32; j += 2) {
                p0 = fmaf(kr[j], vv[j], p0);
                p1 = fmaf(kr[j + 1], vv[j + 1], p1);
            }
            sm_ph[half][r] = p0 + p1;
        }
        __syncthreads();
        if (tid < 512) {
            float p = sm_ph[0][tid] + sm_ph[1][tid];
            sm_u[tid] = sm_mask[tid] * (a / p);
        }
        __syncthreads();
        {
            const float* kc = sK + (rg * 32) * KST + o;
            const float* uu = sm_u + rg * 32;
            float va = 0.f;
            #pragma unroll
            for (int j = 0; j < 32; ++j) va = fmaf(uu[j], kc[j * KST], va);
            sm_vacc[rg][o] = va;
        }
        __syncthreads();
        float own = 0.f;
        if (tid < OUT_SIZE) {
            #pragma unroll
            for (int w = 0; w < 16; ++w) own += sm_vacc[w][tid];
            sm_exch[it & 1][tid] = own;
        }
        asm volatile("barrier.cluster.arrive.aligned;" ::: "memory");
        asm volatile("barrier.cluster.wait.aligned;" ::: "memory");
        if (tid < OUT_SIZE) {
            uint32_t la = smem_u32(&sm_exch[it & 1][tid]);
            uint32_t pa;
            asm("mapa.shared::cluster.u32 %0, %1, %2;" : "=r"(pa) : "r"(la), "r"(1u - rank));
            float pv;
            asm volatile("ld.shared::cluster.f32 %0, [%1];" : "=f"(pv) : "r"(pa));
            sm_v[tid] = 1.0f / (own + pv);
        }
        __syncthreads();
    }

    if (rank == 0 && tid < OUT_SIZE) g_v[(size_t)n * OUT_SIZE + tid] = sm_v[tid];

    #pragma unroll
    for (int pass = 0; pass < 2; ++pass) {
        int oo = pass * 32 + wid;
        size_t obase = (((size_t)n * OUT_SIZE + oo) * IN_SIZE + srow0) >> 1;
        uint32_t* dh = (uint32_t*)g_kT_hi + obase;
        uint32_t* dl = (uint32_t*)g_kT_lo + obase;
        #pragma unroll
        for (int k = 0; k < 8; ++k) {
            int sr = 64 * k + 2 * lane;
            float w0 = sm_u[sr]     * sK[sr * KST + oo];
            float w1 = sm_u[sr + 1] * sK[(sr + 1) * KST + oo];
            __nv_bfloat16 h0, l0, h1, l1;
            split2(w0, h0, l0); split2(w1, h1, l1);
            dh[32 * k + lane] = pack2(h0, h1);
            dl[32 * k + lane] = pack2(l0, l1);
        }
    }

    asm volatile("barrier.cluster.arrive.aligned;" ::: "memory");
    asm volatile("barrier.cluster.wait.aligned;" ::: "memory");
}

// ---------------------------------------------------------------------------
// Kernel 4: attention head-batched: CTA = (d-half 128, b).
// M=128(d) N=256(h,o) K=1024(s), 16 chunks. Two-pass v-scale+transpose epilogue.
// ---------------------------------------------------------------------------
__global__ __launch_bounds__(512, 1) void attn_mma() {
    extern __shared__ char dyn[];
    __nv_bfloat16* Ah = (__nv_bfloat16*)(dyn + OFF2_AH);
    __nv_bfloat16* Al = (__nv_bfloat16*)(dyn + OFF2_AL);
    __nv_bfloat16* Bh = (__nv_bfloat16*)(dyn + OFF2_BH);
    __nv_bfloat16* Bl = (__nv_bfloat16*)(dyn + OFF2_BL);
    __shared__ float s_v[256];

    int tid = threadIdx.x, lane = tid & 31, wid = tid >> 5;
    int wm = wid & 3, wn = wid >> 2;
    int b = blockIdx.y;
    int dhalf = blockIdx.x;
    int d0 = dhalf * 128;

    if (tid < 256) s_v[tid] = g_v[(size_t)b * 256 + tid];

    const __nv_bfloat16* xh = g_xT_hi + ((size_t)b * IN_DIM + d0) * IN_SIZE;
    const __nv_bfloat16* xl = g_xT_lo + ((size_t)b * IN_DIM + d0) * IN_SIZE;
    const __nv_bfloat16* kh = g_kT_hi + (size_t)b * 256 * IN_SIZE;
    const __nv_bfloat16* kl = g_kT_lo + (size_t)b * 256 * IN_SIZE;

    uint32_t aBaseH = smem_u32(Ah) + ((wm * 32 + (lane & 15)) * RS + (lane >> 4) * 8) * 2;
    uint32_t aBaseL = aBaseH + A2_BYTES;
    uint32_t bBaseH = smem_u32(Bh) + ((wn * 64 + (lane & 15)) * RS + (lane >> 4) * 8) * 2;
    uint32_t bBaseL = bBaseH + B2_BYTES;

    float c[2][8][4];
    #pragma unroll
    for (int f = 0; f < 2; ++f)
        #pragma unroll
        for (int g = 0; g < 8; ++g)
            #pragma unroll
            for (int q = 0; q < 4; ++q) c[f][g][q] = 0.f;

    for (int ch = 0; ch < 16; ++ch) {
        int s0 = ch * 64;
        #pragma unroll
        for (int i = 0; i < 2; ++i) {
            int vi = i * 512 + tid;
            int row = vi >> 3, cu = vi & 7;
            size_t goff = (size_t)row * IN_SIZE + s0 + cu * 8;
            int off = row * RS + cu * 8;
            *(uint4*)(Ah + off) = *(const uint4*)(xh + goff);
            *(uint4*)(Al + off) = *(const uint4*)(xl + goff);
        }
        #pragma unroll
        for (int i = 0; i < 4; ++i) {
            int vi = i * 512 + tid;
            int row = vi >> 3, cu = vi & 7;
            size_t goff = (size_t)row * IN_SIZE + s0 + cu * 8;
            int off = row * RS + cu * 8;
            *(uint4*)(Bh + off) = *(const uint4*)(kh + goff);
            *(uint4*)(Bl + off) = *(const uint4*)(kl + goff);
        }
        __syncthreads();
        #pragma unroll
        for (int ks = 0; ks < 4; ++ks) {
            uint32_t ah[2][4], al[2][4];
            #pragma unroll
            for (int f = 0; f < 2; ++f) {
                uint32_t o = (uint32_t)(f * 16 * RS + ks * 16) * 2;
                ldsm4(ah[f], aBaseH + o);
                ldsm4(al[f], aBaseL + o);
            }
            #pragma unroll
            for (int gp = 0; gp < 4; ++gp) {
                uint32_t rh[4], rl[4];
                uint32_t o = (uint32_t)(gp * 16 * RS + ks * 16) * 2;
                ldsm4(rh, bBaseH + o);
                ldsm4(rl, bBaseL + o);
                uint32_t bh0[2] = {rh[0], rh[2]}, bh1[2] = {rh[1], rh[3]};
                uint32_t bl0[2] = {rl[0], rl[2]}, bl1[2] = {rl[1], rl[3]};
                #pragma unroll
                for (int f = 0; f < 2; ++f) {
                    mma16816(c[f][2 * gp],     ah[f], bh0);
                    mma16816(c[f][2 * gp],     ah[f], bl0);
                    mma16816(c[f][2 * gp],     al[f], bh0);
                    mma16816(c[f][2 * gp + 1], ah[f], bh1);
                    mma16816(c[f][2 * gp + 1], ah[f], bl1);
                    mma16816(c[f][2 * gp + 1], al[f], bh1);
                }
            }
        }
        __syncthreads();
    }

    // Two-pass epilogue: pass p covers cols p*128..p*128+127 (2 heads).
    float* smF = (float*)dyn;    // 128 x 129 fp32 = 66048 B
    #pragma unroll
    for (int p = 0; p < 2; ++p) {
        __syncthreads();
        if ((wn >> 1) == p) {
            #pragma unroll
            for (int f = 0; f < 2; ++f) {
                int dl = wm * 32 + f * 16 + (lane >> 2);
                #pragma unroll
                for (int g = 0; g < 8; ++g) {
                    int col = wn * 64 + g * 8 + (lane & 3) * 2;
                    int colL = col - p * 128;
                    smF[dl * 129 + colL]           = s_v[col]     * c[f][g][0];
                    smF[dl * 129 + colL + 1]       = s_v[col + 1] * c[f][g][1];
                    smF[(dl + 8) * 129 + colL]     = s_v[col]     * c[f][g][2];
                    smF[(dl + 8) * 129 + colL + 1] = s_v[col + 1] * c[f][g][3];
                }
            }
        }
        __syncthreads();
        {
            int colL = tid >> 2;
            int dseg = (tid & 3) * 32;
            int col = p * 128 + colL;
            int h = col >> 6, o = col & 63;
            size_t rowbase = ((size_t)(b * 64 + o)) * HID + h * IN_DIM + d0 + dseg;
            #pragma unroll
            for (int j = 0; j < 8; ++j) {
                float f0 = smF[(dseg + 4 * j + 0) * 129 + colL];
                float f1 = smF[(dseg + 4 * j + 1) * 129 + colL];
                float f2 = smF[(dseg + 4 * j + 2) * 129 + colL];
                float f3 = smF[(dseg + 4 * j + 3) * 129 + colL];
                __nv_bfloat16 h0, h1, h2, h3, l0, l1, l2, l3;
                split2(f0, h0, l0); split2(f1, h1, l1);
                split2(f2, h2, l2); split2(f3, h3, l3);
                *(uint2*)(g_att_hi + rowbase + 4 * j) = make_uint2(pack2(h0, h1), pack2(h2, h3));
                *(uint2*)(g_att_lo + rowbase + 4 * j) = make_uint2(pack2(l0, l1), pack2(l2, l3));
            }
        }
    }
}

// ---------------------------------------------------------------------------
// Kernel 5: out = relu(att @ lin_wᵀ + lin_b), bf16 split-2 HMMA (unchanged).
// ---------------------------------------------------------------------------
__global__ __launch_bounds__(256) void linear_mma(const float* __restrict__ lb,
                                                  float* __restrict__ out) {
    extern __shared__ char dyn[];
    __nv_bfloat16* Ah = (__nv_bfloat16*)(dyn + OFF_AH);
    __nv_bfloat16* Al = (__nv_bfloat16*)(dyn + OFF_AL);
    __nv_bfloat16* Bh = (__nv_bfloat16*)(dyn + OFF_BH);
    __nv_bfloat16* Bl = (__nv_bfloat16*)(dyn + OFF_BL);

    int tid = threadIdx.x, lane = tid & 31, wid = tid >> 5;
    int wm = wid & 3, wn = wid >> 2;
    int m0 = blockIdx.x * 128;
    int n0 = blockIdx.y * 64;

    const __nv_bfloat16* ath = g_att_hi + (size_t)m0 * HID;
    const __nv_bfloat16* atl = g_att_lo + (size_t)m0 * HID;
    const __nv_bfloat16* lwh = g_lw_hi + (size_t)n0 * HID;
    const __nv_bfloat16* lwl = g_lw_lo + (size_t)n0 * HID;

    uint32_t aBaseH = smem_u32(Ah) + ((wm * 32 + (lane & 15)) * RS + (lane >> 4) * 8) * 2;
    uint32_t aBaseL = aBaseH + (OFF_AL - OFF_AH);
    uint32_t bBaseH = smem_u32(Bh) + ((wn * 32 + (lane & 7)) * RS + ((lane >> 3) & 1) * 8) * 2;
    uint32_t bBaseL = bBaseH + (OFF_BL - OFF_BH);

    float c[2][4][4];
    #pragma unroll
    for (int f = 0; f < 2; ++f)
        #pragma unroll
        for (int g = 0; g < 4; ++g)
            #pragma unroll
            for (int q = 0; q < 4; ++q) c[f][g][q] = 0.f;

    for (int ch = 0; ch < 16; ++ch) {
        int k0 = ch * 64;
        #pragma unroll
        for (int i = 0; i < 4; ++i) {
            int vi = i * 256 + tid;
            int row = vi >> 3, cu = vi & 7;
            size_t goff = (size_t)row * HID + k0 + cu * 8;
            int off = row * RS + cu * 8;
            *(uint4*)(Ah + off) = *(const uint4*)(ath + goff);
            *(uint4*)(Al + off) = *(const uint4*)(atl + goff);
        }
        #pragma unroll
        for (int i = 0; i < 2; ++i) {
            int vi = i * 256 + tid;
            int row = vi >> 3, cu = vi & 7;
            size_t goff = (size_t)row * HID + k0 + cu * 8;
            int off = row * RS + cu * 8;
            *(uint4*)(Bh + off) = *(const uint4*)(lwh + goff);
            *(uint4*)(Bl + off) = *(const uint4*)(lwl + goff);
        }
        __syncthreads();
        #pragma unroll
        for (int ks = 0; ks < 4; ++ks) {
            uint32_t ah[2][4], al[2][4], bh[4][2], bl[4][2];
            #pragma unroll
            for (int f = 0; f < 2; ++f) {
                uint32_t o = (uint32_t)(f * 16 * RS + ks * 16) * 2;
                ldsm4(ah[f], aBaseH + o);
                ldsm4(al[f], aBaseL + o);
            }
            #pragma unroll
            for (int g = 0; g < 4; ++g) {
                uint32_t o = (uint32_t)(g * 8 * RS + ks * 16) * 2;
                ldsm2(bh[g], bBaseH + o);
                ldsm2(bl[g], bBaseL + o);
            }
            #pragma unroll
            for (int f = 0; f < 2; ++f)
                #pragma unroll
                for (int g = 0; g < 4; ++g) {
                    mma16816(c[f][g], ah[f], bh[g]);
                    mma16816(c[f][g], ah[f], bl[g]);
                    mma16816(c[f][g], al[f], bh[g]);
                }
        }
        __syncthreads();
    }

    #pragma unroll
    for (int f = 0; f < 2; ++f) {
        int m = m0 + wm * 32 + f * 16 + (lane >> 2);
        #pragma unroll
        for (int g = 0; g < 4; ++g) {
            int nn = n0 + wn * 32 + g * 8 + (lane & 3) * 2;
            float b0 = lb[nn], b1 = lb[nn + 1];
            float r0 = c[f][g][0] + b0, r1 = c[f][g][1] + b1;
            float r2 = c[f][g][2] + b0, r3 = c[f][g][3] + b1;
            *(float2*)(out + (size_t)m * OUT_DIM + nn) =
                make_float2(r0 > 0.f ? r0 : 0.f, r1 > 0.f ? r1 : 0.f);
            *(float2*)(out + (size_t)(m + 8) * OUT_DIM + nn) =
                make_float2(r2 > 0.f ? r2 : 0.f, r3 > 0.f ? r3 : 0.f);
        }
    }
}

// ---------------------------------------------------------------------------
// Launch
// ---------------------------------------------------------------------------
extern "C" void kernel_launch(void* const* d_in, const int* in_sizes, int n_in,
                              void* d_out, int out_size) {
    const float* x    = (const float*)d_in[0];
    const int*   mask = (const int*)d_in[1];
    const float* W    = (const float*)d_in[2];
    const float* lw   = (const float*)d_in[3];
    const float* lb   = (const float*)d_in[4];
    float*       out  = (float*)d_out;

    cudaFuncSetAttribute(gemm_k_mma, cudaFuncAttributeMaxDynamicSharedMemorySize, DSMEM2);
    cudaFuncSetAttribute(attn_mma,   cudaFuncAttributeMaxDynamicSharedMemorySize, DSMEM2);
    cudaFuncSetAttribute(linear_mma, cudaFuncAttributeMaxDynamicSharedMemorySize, DSMEM_BYTES);
    cudaFuncSetAttribute(sinkhorn_fused, cudaFuncAttributeMaxDynamicSharedMemorySize, SINK_BYTES);

    xsplit_kernel<<<dim3(IN_SIZE / 64, IN_DIM / 64, BATCH), 256>>>(x);
    wsplit_kernel<<<(HEADS * OUT_SIZE * IN_DIM / 4) / 256, 256>>>(W);
    lwsplit_kernel<<<(OUT_DIM * HID / 4) / 256, 256>>>(lw);
    gemm_k_mma<<<dim3(IN_SIZE / 128, BATCH), 512, DSMEM2>>>(x);
    sinkhorn_fused<<<NMAT * 2, 1024, SINK_BYTES>>>(mask);
    attn_mma<<<dim3(2, BATCH), 512, DSMEM2>>>();
    linear_mma<<<dim3(BATCH * OUT_SIZE / 128, OUT_DIM / 64), 256, DSMEM_BYTES>>>(lb, out);
}

// round 12
// speedup vs baseline: 1.0687x; 1.0687x over previous
#include <cuda_runtime.h>
#include <cuda_bf16.h>
#include <math.h>
#include <stdint.h>

#define BATCH    64
#define IN_SIZE  1024
#define IN_DIM   256
#define HEADS    4
#define OUT_SIZE 64
#define OUT_DIM  256
#define NMAT     (BATCH * HEADS)     /* 256 */
#define HID      (HEADS * IN_DIM)    /* 1024 */
#define MAX_ITER 10

// ---------------------------------------------------------------------------
// Scratch
// ---------------------------------------------------------------------------
__device__ float g_K[(size_t)NMAT * IN_SIZE * OUT_SIZE];        // 64 MB [n][s][o]
__device__ float g_v[(size_t)NMAT * OUT_SIZE];
__device__ __nv_bfloat16 g_xT_hi[(size_t)BATCH * IN_DIM * IN_SIZE];   // [b][d][s]
__device__ __nv_bfloat16 g_xT_lo[(size_t)BATCH * IN_DIM * IN_SIZE];
__device__ __nv_bfloat16 g_kT_hi[(size_t)NMAT * OUT_SIZE * IN_SIZE];  // [n][o][s]
__device__ __nv_bfloat16 g_kT_lo[(size_t)NMAT * OUT_SIZE * IN_SIZE];
__device__ __nv_bfloat16 g_att_hi[(size_t)BATCH * OUT_SIZE * HID];    // [m][k]
__device__ __nv_bfloat16 g_att_lo[(size_t)BATCH * OUT_SIZE * HID];
__device__ __nv_bfloat16 g_lw_hi[(size_t)OUT_DIM * HID];              // [nn][k]
__device__ __nv_bfloat16 g_lw_lo[(size_t)OUT_DIM * HID];

// ---------------------------------------------------------------------------
// Helpers (base-target PTX only)
// ---------------------------------------------------------------------------
__device__ __forceinline__ uint32_t smem_u32(const void* p) {
    uint32_t a;
    asm("{ .reg .u64 t; cvta.to.shared.u64 t, %1; cvt.u32.u64 %0, t; }" : "=r"(a) : "l"(p));
    return a;
}
__device__ __forceinline__ void ldsm4(uint32_t* r, uint32_t a) {
    asm volatile("ldmatrix.sync.aligned.m8n8.x4.shared.b16 {%0,%1,%2,%3}, [%4];"
        : "=r"(r[0]), "=r"(r[1]), "=r"(r[2]), "=r"(r[3]) : "r"(a));
}
__device__ __forceinline__ void ldsm2(uint32_t* r, uint32_t a) {
    asm volatile("ldmatrix.sync.aligned.m8n8.x2.shared.b16 {%0,%1}, [%2];"
        : "=r"(r[0]), "=r"(r[1]) : "r"(a));
}
__device__ __forceinline__ void mma16816(float* c, const uint32_t* a, const uint32_t* b) {
    asm volatile(
        "mma.sync.aligned.m16n8k16.row.col.f32.bf16.bf16.f32 "
        "{%0,%1,%2,%3}, {%4,%5,%6,%7}, {%8,%9}, {%0,%1,%2,%3};"
        : "+f"(c[0]), "+f"(c[1]), "+f"(c[2]), "+f"(c[3])
        : "r"(a[0]), "r"(a[1]), "r"(a[2]), "r"(a[3]), "r"(b[0]), "r"(b[1]));
}
__device__ __forceinline__ uint32_t pack2(__nv_bfloat16 a, __nv_bfloat16 b) {
    uint16_t ua = *(uint16_t*)&a, ub = *(uint16_t*)&b;
    return (uint32_t)ua | ((uint32_t)ub << 16);
}
__device__ __forceinline__ void split2(float f, __nv_bfloat16& h, __nv_bfloat16& l) {
    h = __float2bfloat16(f);
    l = __float2bfloat16(f - __bfloat162float(h));
}

// Padded bf16 SMEM tiles for MMA kernels: row stride 72 elems (144 B).
#define RS 72
#define OFF_AH 0
#define OFF_AL (128 * RS * 2)
#define OFF_BH (2 * 128 * RS * 2)
#define OFF_BL (2 * 128 * RS * 2 + 64 * RS * 2)
#define DSMEM_BYTES (2 * 128 * RS * 2 + 2 * 64 * RS * 2)   /* 55296 */

// Sinkhorn: 4-CTA cluster, 256 rows per CTA, stride-67 padded K.
#define KST 67
#define SROWS 256
#define SINK_BYTES (SROWS * KST * 4)   /* 68608 */
#define CLU 4

// ---------------------------------------------------------------------------
// Kernel 1: K = exp(10 * x·Wᵀ), bf16 split-2 HMMA (R10 known-good).
// CTA = (s-tile 128, n). M=128(s) N=64(o) K=256(d).
// ---------------------------------------------------------------------------
__global__ __launch_bounds__(256) void gemm_k_mma(const float* __restrict__ x,
                                                  const float* __restrict__ W) {
    extern __shared__ char dyn[];
    __nv_bfloat16* Ah = (__nv_bfloat16*)(dyn + OFF_AH);
    __nv_bfloat16* Al = (__nv_bfloat16*)(dyn + OFF_AL);
    __nv_bfloat16* Bh = (__nv_bfloat16*)(dyn + OFF_BH);
    __nv_bfloat16* Bl = (__nv_bfloat16*)(dyn + OFF_BL);

    int tid = threadIdx.x, lane = tid & 31, wid = tid >> 5;
    int wm = wid & 3, wn = wid >> 2;
    int n = blockIdx.y, b = n >> 2, h = n & 3;
    int s0 = blockIdx.x * 128;
    const float* xg = x + ((size_t)b * IN_SIZE + s0) * IN_DIM;
    const float* wg = W + (size_t)h * OUT_SIZE * IN_DIM;

    uint32_t aBaseH = smem_u32(Ah) + ((wm * 32 + (lane & 15)) * RS + (lane >> 4) * 8) * 2;
    uint32_t aBaseL = aBaseH + (OFF_AL - OFF_AH);
    uint32_t bBaseH = smem_u32(Bh) + ((wn * 32 + (lane & 7)) * RS + ((lane >> 3) & 1) * 8) * 2;
    uint32_t bBaseL = bBaseH + (OFF_BL - OFF_BH);

    float c[2][4][4];
    #pragma unroll
    for (int f = 0; f < 2; ++f)
        #pragma unroll
        for (int g = 0; g < 4; ++g)
            #pragma unroll
            for (int q = 0; q < 4; ++q) c[f][g][q] = 0.f;

    for (int ch = 0; ch < 4; ++ch) {
        int d0 = ch * 64;
        #pragma unroll
        for (int i = 0; i < 8; ++i) {
            int vi = i * 256 + tid;
            int row = vi >> 4, c4 = (vi & 15) * 4;
            float4 v = *(const float4*)(xg + (size_t)row * IN_DIM + d0 + c4);
            __nv_bfloat16 h0, h1, h2, h3, l0, l1, l2, l3;
            split2(v.x, h0, l0); split2(v.y, h1, l1);
            split2(v.z, h2, l2); split2(v.w, h3, l3);
            int off = row * RS + c4;
            *(uint2*)(Ah + off) = make_uint2(pack2(h0, h1), pack2(h2, h3));
            *(uint2*)(Al + off) = make_uint2(pack2(l0, l1), pack2(l2, l3));
        }
        #pragma unroll
        for (int i = 0; i < 4; ++i) {
            int vi = i * 256 + tid;
            int row = vi >> 4, c4 = (vi & 15) * 4;
            float4 v = *(const float4*)(wg + (size_t)row * IN_DIM + d0 + c4);
            __nv_bfloat16 h0, h1, h2, h3, l0, l1, l2, l3;
            split2(v.x, h0, l0); split2(v.y, h1, l1);
            split2(v.z, h2, l2); split2(v.w, h3, l3);
            int off = row * RS + c4;
            *(uint2*)(Bh + off) = make_uint2(pack2(h0, h1), pack2(h2, h3));
            *(uint2*)(Bl + off) = make_uint2(pack2(l0, l1), pack2(l2, l3));
        }
        __syncthreads();
        #pragma unroll
        for (int ks = 0; ks < 4; ++ks) {
            uint32_t ah[2][4], al[2][4], bh[4][2], bl[4][2];
            #pragma unroll
            for (int f = 0; f < 2; ++f) {
                uint32_t o = (uint32_t)(f * 16 * RS + ks * 16) * 2;
                ldsm4(ah[f], aBaseH + o);
                ldsm4(al[f], aBaseL + o);
            }
            #pragma unroll
            for (int g = 0; g < 4; ++g) {
                uint32_t o = (uint32_t)(g * 8 * RS + ks * 16) * 2;
                ldsm2(bh[g], bBaseH + o);
                ldsm2(bl[g], bBaseL + o);
            }
            #pragma unroll
            for (int f = 0; f < 2; ++f)
                #pragma unroll
                for (int g = 0; g < 4; ++g) {
                    mma16816(c[f][g], ah[f], bh[g]);
                    mma16816(c[f][g], ah[f], bl[g]);
                    mma16816(c[f][g], al[f], bh[g]);
                }
        }
        __syncthreads();
    }

    #pragma unroll
    for (int f = 0; f < 2; ++f) {
        int r0 = s0 + wm * 32 + f * 16 + (lane >> 2);
        #pragma unroll
        for (int g = 0; g < 4; ++g) {
            int o = wn * 32 + g * 8 + (lane & 3) * 2;
            float* p0 = g_K + ((size_t)n * IN_SIZE + r0) * OUT_SIZE + o;
            float* p1 = p0 + 8 * OUT_SIZE;
            *(float2*)p0 = make_float2(expf(c[f][g][0] * 10.f), expf(c[f][g][1] * 10.f));
            *(float2*)p1 = make_float2(expf(c[f][g][2] * 10.f), expf(c[f][g][3] * 10.f));
        }
    }
}

// ---------------------------------------------------------------------------
// Kernel 2: x[b][s][d] fp32 -> g_xT_hi/lo[b][d][s] bf16
// ---------------------------------------------------------------------------
__global__ __launch_bounds__(256) void xsplit_kernel(const float* __restrict__ x) {
    __shared__ float sm[64][65];
    int tid = threadIdx.x;
    int s0 = blockIdx.x * 64, d0 = blockIdx.y * 64, b = blockIdx.z;
    const float* xb = x + ((size_t)b * IN_SIZE + s0) * IN_DIM + d0;
    #pragma unroll
    for (int i = 0; i < 4; ++i) {
        int vi = i * 256 + tid;
        int rs = vi >> 4, c4 = (vi & 15) * 4;
        float4 v = *(const float4*)(xb + (size_t)rs * IN_DIM + c4);
        sm[rs][c4] = v.x; sm[rs][c4 + 1] = v.y; sm[rs][c4 + 2] = v.z; sm[rs][c4 + 3] = v.w;
    }
    __syncthreads();
    #pragma unroll
    for (int i = 0; i < 4; ++i) {
        int vi = i * 256 + tid;
        int rd = vi >> 4, s4 = (vi & 15) * 4;
        __nv_bfloat16 h[4], l[4];
        #pragma unroll
        for (int j = 0; j < 4; ++j) split2(sm[s4 + j][rd], h[j], l[j]);
        size_t off = ((size_t)b * IN_DIM + d0 + rd) * IN_SIZE + s0 + s4;
        *(uint2*)(g_xT_hi + off) = make_uint2(pack2(h[0], h[1]), pack2(h[2], h[3]));
        *(uint2*)(g_xT_lo + off) = make_uint2(pack2(l[0], l[1]), pack2(l[2], l[3]));
    }
}

// ---------------------------------------------------------------------------
// Kernel 3: Sinkhorn fused, 4-CTA cluster, 256 rows/CTA, 512 threads.
// Occupancy goal: 68.6 KB SMEM + <=64 regs -> 2 CTAs/SM resident.
// ---------------------------------------------------------------------------
__global__ void __cluster_dims__(CLU, 1, 1) __launch_bounds__(512, 2)
sinkhorn_fused(const int* __restrict__ mask) {
    extern __shared__ float sK[];          // 256 x 67 fp32 = 68608 B
    __shared__ float sm_mask[SROWS];
    __shared__ float sm_v[OUT_SIZE];
    __shared__ float sm_u[SROWS];
    __shared__ float sm_ph[2][SROWS];
    __shared__ float sm_vacc[8][OUT_SIZE];
    __shared__ float sm_exch[2][OUT_SIZE];
    __shared__ float sm_red[16];
    __shared__ float sm_a;

    int tid = threadIdx.x, lane = tid & 31, wid = tid >> 5;
    uint32_t rank;
    asm("mov.u32 %0, %%cluster_ctarank;" : "=r"(rank));
    int n = blockIdx.x >> 2;
    int b = n >> 2;
    int srow0 = (int)rank * SROWS;

    // a = 64 / sum(mask): every thread reads 2 of the 1024 entries.
    const int* mb = mask + (size_t)b * IN_SIZE;
    float s = ((mb[tid] != 0) ? 1.f : 0.f) + ((mb[tid + 512] != 0) ? 1.f : 0.f);
    #pragma unroll
    for (int off = 16; off; off >>= 1) s += __shfl_xor_sync(0xffffffffu, s, off);
    if (lane == 0) sm_red[wid] = s;
    // local mask rows
    if (tid < SROWS) sm_mask[tid] = (mb[srow0 + tid] != 0) ? 1.f : 0.f;
    if (tid < OUT_SIZE) sm_v[tid] = 1.0f;
    __syncthreads();
    if (tid == 0) {
        float t = 0.f;
        #pragma unroll
        for (int w = 0; w < 16; ++w) t += sm_red[w];
        sm_a = (float)OUT_SIZE / t;
    }

    // Load local K slice (256 x 64 fp32 = 64 KB) into padded SMEM
    {
        const float4* g4 = (const float4*)(g_K + ((size_t)n * IN_SIZE + srow0) * OUT_SIZE);
        #pragma unroll
        for (int i = 0; i < 8; ++i) {
            int idx = i * 512 + tid;
            int row = idx >> 4, q = idx & 15;
            float4 v = g4[idx];
            float* d = sK + row * KST + q * 4;
            d[0] = v.x; d[1] = v.y; d[2] = v.z; d[3] = v.w;
        }
    }
    __syncthreads();
    float a = sm_a;

    int half = tid >> 8;               // 0/1: o-half for u-pass
    int r = tid & 255;                 // row for u-pass
    int o = tid & 63, rg = tid >> 6;   // v-pass: 8 row-groups x 64 o

    for (int it = 0; it < MAX_ITER; ++it) {
        // --- u-pass: thread = (row, o-half), 32 scalar conflict-free LDS ---
        {
            const float* kr = sK + r * KST + half * 32;
            const float* vv = sm_v + half * 32;
            float p0 = 0.f, p1 = 0.f;
            #pragma unroll
            for (int j = 0; j < 32; j += 2) {
                p0 = fmaf(kr[j], vv[j], p0);
                p1 = fmaf(kr[j + 1], vv[j + 1], p1);
            }
            sm_ph[half][r] = p0 + p1;
        }
        __syncthreads();
        if (tid < SROWS) {
            float p = sm_ph[0][tid] + sm_ph[1][tid];
            sm_u[tid] = sm_mask[tid] * (a / p);
        }
        __syncthreads();
        // --- v-pass: thread = (o, row-group of 32), conflict-free ---
        {
            const float* kc = sK + (rg * 32) * KST + o;
            const float* uu = sm_u + rg * 32;
            float va = 0.f;
            #pragma unroll
            for (int j = 0; j < 32; ++j) va = fmaf(uu[j], kc[j * KST], va);
            sm_vacc[rg][o] = va;
        }
        __syncthreads();
        float own = 0.f;
        if (tid < OUT_SIZE) {
            #pragma unroll
            for (int w = 0; w < 8; ++w) own += sm_vacc[w][tid];
            sm_exch[it & 1][tid] = own;
        }
        // Cluster barrier: release own partial, acquire peers' (ALL threads).
        asm volatile("barrier.cluster.arrive.aligned;" ::: "memory");
        asm volatile("barrier.cluster.wait.aligned;" ::: "memory");
        if (tid < OUT_SIZE) {
            uint32_t la = smem_u32(&sm_exch[it & 1][tid]);
            float tot = own;
            #pragma unroll
            for (int pr = 1; pr < CLU; ++pr) {
                uint32_t tr = (rank + pr) & (CLU - 1);
                uint32_t pa;
                asm("mapa.shared::cluster.u32 %0, %1, %2;" : "=r"(pa) : "r"(la), "r"(tr));
                float pv;
                asm volatile("ld.shared::cluster.f32 %0, [%1];" : "=f"(pv) : "r"(pa));
                tot += pv;
            }
            sm_v[tid] = 1.0f / tot;
        }
        __syncthreads();
    }

    // Epilogue 1: v out (rank 0)
    if (rank == 0 && tid < OUT_SIZE) g_v[(size_t)n * OUT_SIZE + tid] = sm_v[tid];

    // Epilogue 2: (u⊙K)ᵀ bf16 hi/lo; 16 warps x 4 passes cover 64 o-rows.
    #pragma unroll
    for (int pass = 0; pass < 4; ++pass) {
        int oo = pass * 16 + wid;
        size_t obase = (((size_t)n * OUT_SIZE + oo) * IN_SIZE + srow0) >> 1;  // uint idx
        uint32_t* dh = (uint32_t*)g_kT_hi + obase;
        uint32_t* dl = (uint32_t*)g_kT_lo + obase;
        #pragma unroll
        for (int k = 0; k < 4; ++k) {
            int sr = 64 * k + 2 * lane;
            float w0 = sm_u[sr]     * sK[sr * KST + oo];
            float w1 = sm_u[sr + 1] * sK[(sr + 1) * KST + oo];
            __nv_bfloat16 h0, l0, h1, l1;
            split2(w0, h0, l0); split2(w1, h1, l1);
            dh[32 * k + lane] = pack2(h0, h1);
            dl[32 * k + lane] = pack2(l0, l1);
        }
    }

    // No CTA may exit while a peer might still read DSMEM.
    asm volatile("barrier.cluster.arrive.aligned;" ::: "memory");
    asm volatile("barrier.cluster.wait.aligned;" ::: "memory");
}

// ---------------------------------------------------------------------------
// Kernel 4: attention (R10 known-good): D[d,o] = Σ_s xT[d,s]·(uK)T[o,s].
// ---------------------------------------------------------------------------
__global__ __launch_bounds__(256) void attn_mma() {
    extern __shared__ char dyn[];
    __nv_bfloat16* Ah = (__nv_bfloat16*)(dyn + OFF_AH);
    __nv_bfloat16* Al = (__nv_bfloat16*)(dyn + OFF_AL);
    __nv_bfloat16* Bh = (__nv_bfloat16*)(dyn + OFF_BH);
    __nv_bfloat16* Bl = (__nv_bfloat16*)(dyn + OFF_BL);
    __shared__ float s_v[OUT_SIZE];

    int tid = threadIdx.x, lane = tid & 31, wid = tid >> 5;
    int wm = wid & 3, wn = wid >> 2;
    int n = blockIdx.y, b = n >> 2, h = n & 3;
    int d0 = blockIdx.x * 128;

    if (tid < OUT_SIZE) s_v[tid] = g_v[(size_t)n * OUT_SIZE + tid];

    const __nv_bfloat16* xh = g_xT_hi + ((size_t)b * IN_DIM + d0) * IN_SIZE;
    const __nv_bfloat16* xl = g_xT_lo + ((size_t)b * IN_DIM + d0) * IN_SIZE;
    const __nv_bfloat16* kh = g_kT_hi + (size_t)n * OUT_SIZE * IN_SIZE;
    const __nv_bfloat16* kl = g_kT_lo + (size_t)n * OUT_SIZE * IN_SIZE;

    uint32_t aBaseH = smem_u32(Ah) + ((wm * 32 + (lane & 15)) * RS + (lane >> 4) * 8) * 2;
    uint32_t aBaseL = aBaseH + (OFF_AL - OFF_AH);
    uint32_t bBaseH = smem_u32(Bh) + ((wn * 32 + (lane & 7)) * RS + ((lane >> 3) & 1) * 8) * 2;
    uint32_t bBaseL = bBaseH + (OFF_BL - OFF_BH);

    float c[2][4][4];
    #pragma unroll
    for (int f = 0; f < 2; ++f)
        #pragma unroll
        for (int g = 0; g < 4; ++g)
            #pragma unroll
            for (int q = 0; q < 4; ++q) c[f][g][q] = 0.f;

    for (int ch = 0; ch < 16; ++ch) {
        int s0 = ch * 64;
        #pragma unroll
        for (int i = 0; i < 4; ++i) {
            int vi = i * 256 + tid;
            int row = vi >> 3, cu = vi & 7;
            size_t goff = (size_t)row * IN_SIZE + s0 + cu * 8;
            int off = row * RS + cu * 8;
            *(uint4*)(Ah + off) = *(const uint4*)(xh + goff);
            *(uint4*)(Al + off) = *(const uint4*)(xl + goff);
        }
        #pragma unroll
        for (int i = 0; i < 2; ++i) {
            int vi = i * 256 + tid;
            int row = vi >> 3, cu = vi & 7;
            size_t goff = (size_t)row * IN_SIZE + s0 + cu * 8;
            int off = row * RS + cu * 8;
            *(uint4*)(Bh + off) = *(const uint4*)(kh + goff);
            *(uint4*)(Bl + off) = *(const uint4*)(kl + goff);
        }
        __syncthreads();
        #pragma unroll
        for (int ks = 0; ks < 4; ++ks) {
            uint32_t ah[2][4], al[2][4], bh[4][2], bl[4][2];
            #pragma unroll
            for (int f = 0; f < 2; ++f) {
                uint32_t o = (uint32_t)(f * 16 * RS + ks * 16) * 2;
                ldsm4(ah[f], aBaseH + o);
                ldsm4(al[f], aBaseL + o);
            }
            #pragma unroll
            for (int g = 0; g < 4; ++g) {
                uint32_t o = (uint32_t)(g * 8 * RS + ks * 16) * 2;
                ldsm2(bh[g], bBaseH + o);
                ldsm2(bl[g], bBaseL + o);
            }
            #pragma unroll
            for (int f = 0; f < 2; ++f)
                #pragma unroll
                for (int g = 0; g < 4; ++g) {
                    mma16816(c[f][g], ah[f], bh[g]);
                    mma16816(c[f][g], ah[f], bl[g]);
                    mma16816(c[f][g], al[f], bh[g]);
                }
        }
        __syncthreads();
    }

    // Epilogue: v-scale, transpose via SMEM, emit bf16 hi/lo att[m][k]
    float* smF = (float*)dyn;   // 128 x 65 fp32
    #pragma unroll
    for (int f = 0; f < 2; ++f) {
        int dl = wm * 32 + f * 16 + (lane >> 2);
        #pragma unroll
        for (int g = 0; g < 4; ++g) {
            int o = wn * 32 + g * 8 + (lane & 3) * 2;
            smF[dl * 65 + o]           = s_v[o]     * c[f][g][0];
            smF[dl * 65 + o + 1]       = s_v[o + 1] * c[f][g][1];
            smF[(dl + 8) * 65 + o]     = s_v[o]     * c[f][g][2];
            smF[(dl + 8) * 65 + o + 1] = s_v[o + 1] * c[f][g][3];
        }
    }
    __syncthreads();
    {
        int o = tid >> 2;
        int dseg = (tid & 3) * 32;
        size_t rowbase = ((size_t)b * OUT_SIZE + o) * HID + (size_t)h * IN_DIM + d0 + dseg;
        #pragma unroll
        for (int j = 0; j < 8; ++j) {
            float f0 = smF[(dseg + 4 * j + 0) * 65 + o];
            float f1 = smF[(dseg + 4 * j + 1) * 65 + o];
            float f2 = smF[(dseg + 4 * j + 2) * 65 + o];
            float f3 = smF[(dseg + 4 * j + 3) * 65 + o];
            __nv_bfloat16 h0, h1, h2, h3, l0, l1, l2, l3;
            split2(f0, h0, l0); split2(f1, h1, l1);
            split2(f2, h2, l2); split2(f3, h3, l3);
            *(uint2*)(g_att_hi + rowbase + 4 * j) = make_uint2(pack2(h0, h1), pack2(h2, h3));
            *(uint2*)(g_att_lo + rowbase + 4 * j) = make_uint2(pack2(l0, l1), pack2(l2, l3));
        }
    }
}

// ---------------------------------------------------------------------------
// Kernel 5: lin_w fp32 -> bf16 hi/lo
// ---------------------------------------------------------------------------
__global__ __launch_bounds__(256) void lwsplit_kernel(const float* __restrict__ lw) {
    int i = blockIdx.x * 256 + threadIdx.x;
    float4 v = *(const float4*)(lw + (size_t)i * 4);
    __nv_bfloat16 h0, h1, h2, h3, l0, l1, l2, l3;
    split2(v.x, h0, l0); split2(v.y, h1, l1);
    split2(v.z, h2, l2); split2(v.w, h3, l3);
    *(uint2*)(g_lw_hi + (size_t)i * 4) = make_uint2(pack2(h0, h1), pack2(h2, h3));
    *(uint2*)(g_lw_lo + (size_t)i * 4) = make_uint2(pack2(l0, l1), pack2(l2, l3));
}

// ---------------------------------------------------------------------------
// Kernel 6: out = relu(att @ lin_wᵀ + lin_b), bf16 split-2 HMMA.
// ---------------------------------------------------------------------------
__global__ __launch_bounds__(256) void linear_mma(const float* __restrict__ lb,
                                                  float* __restrict__ out) {
    extern __shared__ char dyn[];
    __nv_bfloat16* Ah = (__nv_bfloat16*)(dyn + OFF_AH);
    __nv_bfloat16* Al = (__nv_bfloat16*)(dyn + OFF_AL);
    __nv_bfloat16* Bh = (__nv_bfloat16*)(dyn + OFF_BH);
    __nv_bfloat16* Bl = (__nv_bfloat16*)(dyn + OFF_BL);

    int tid = threadIdx.x, lane = tid & 31, wid = tid >> 5;
    int wm = wid & 3, wn = wid >> 2;
    int m0 = blockIdx.x * 128;
    int n0 = blockIdx.y * 64;

    const __nv_bfloat16* ath = g_att_hi + (size_t)m0 * HID;
    const __nv_bfloat16* atl = g_att_lo + (size_t)m0 * HID;
    const __nv_bfloat16* lwh = g_lw_hi + (size_t)n0 * HID;
    const __nv_bfloat16* lwl = g_lw_lo + (size_t)n0 * HID;

    uint32_t aBaseH = smem_u32(Ah) + ((wm * 32 + (lane & 15)) * RS + (lane >> 4) * 8) * 2;
    uint32_t aBaseL = aBaseH + (OFF_AL - OFF_AH);
    uint32_t bBaseH = smem_u32(Bh) + ((wn * 32 + (lane & 7)) * RS + ((lane >> 3) & 1) * 8) * 2;
    uint32_t bBaseL = bBaseH + (OFF_BL - OFF_BH);

    float c[2][4][4];
    #pragma unroll
    for (int f = 0; f < 2; ++f)
        #pragma unroll
        for (int g = 0; g < 4; ++g)
            #pragma unroll
            for (int q = 0; q < 4; ++q) c[f][g][q] = 0.f;

    for (int ch = 0; ch < 16; ++ch) {
        int k0 = ch * 64;
        #pragma unroll
        for (int i = 0; i < 4; ++i) {
            int vi = i * 256 + tid;
            int row = vi >> 3, cu = vi & 7;
            size_t goff = (size_t)row * HID + k0 + cu * 8;
            int off = row * RS + cu * 8;
            *(uint4*)(Ah + off) = *(const uint4*)(ath + goff);
            *(uint4*)(Al + off) = *(const uint4*)(atl + goff);
        }
        #pragma unroll
        for (int i = 0; i < 2; ++i) {
            int vi = i * 256 + tid;
            int row = vi >> 3, cu = vi & 7;
            size_t goff = (size_t)row * HID + k0 + cu * 8;
            int off = row * RS + cu * 8;
            *(uint4*)(Bh + off) = *(const uint4*)(lwh + goff);
            *(uint4*)(Bl + off) = *(const uint4*)(lwl + goff);
        }
        __syncthreads();
        #pragma unroll
        for (int ks = 0; ks < 4; ++ks) {
            uint32_t ah[2][4], al[2][4], bh[4][2], bl[4][2];
            #pragma unroll
            for (int f = 0; f < 2; ++f) {
                uint32_t o = (uint32_t)(f * 16 * RS + ks * 16) * 2;
                ldsm4(ah[f], aBaseH + o);
                ldsm4(al[f], aBaseL + o);
            }
            #pragma unroll
            for (int g = 0; g < 4; ++g) {
                uint32_t o = (uint32_t)(g * 8 * RS + ks * 16) * 2;
                ldsm2(bh[g], bBaseH + o);
                ldsm2(bl[g], bBaseL + o);
            }
            #pragma unroll
            for (int f = 0; f < 2; ++f)
                #pragma unroll
                for (int g = 0; g < 4; ++g) {
                    mma16816(c[f][g], ah[f], bh[g]);
                    mma16816(c[f][g], ah[f], bl[g]);
                    mma16816(c[f][g], al[f], bh[g]);
                }
        }
        __syncthreads();
    }

    #pragma unroll
    for (int f = 0; f < 2; ++f) {
        int m = m0 + wm * 32 + f * 16 + (lane >> 2);
        #pragma unroll
        for (int g = 0; g < 4; ++g) {
            int nn = n0 + wn * 32 + g * 8 + (lane & 3) * 2;
            float b0 = lb[nn], b1 = lb[nn + 1];
            float r0 = c[f][g][0] + b0, r1 = c[f][g][1] + b1;
            float r2 = c[f][g][2] + b0, r3 = c[f][g][3] + b1;
            *(float2*)(out + (size_t)m * OUT_DIM + nn) =
                make_float2(r0 > 0.f ? r0 : 0.f, r1 > 0.f ? r1 : 0.f);
            *(float2*)(out + (size_t)(m + 8) * OUT_DIM + nn) =
                make_float2(r2 > 0.f ? r2 : 0.f, r3 > 0.f ? r3 : 0.f);
        }
    }
}

// ---------------------------------------------------------------------------
// Launch
// ---------------------------------------------------------------------------
extern "C" void kernel_launch(void* const* d_in, const int* in_sizes, int n_in,
                              void* d_out, int out_size) {
    const float* x    = (const float*)d_in[0];
    const int*   mask = (const int*)d_in[1];
    const float* W    = (const float*)d_in[2];
    const float* lw   = (const float*)d_in[3];
    const float* lb   = (const float*)d_in[4];
    float*       out  = (float*)d_out;

    cudaFuncSetAttribute(gemm_k_mma, cudaFuncAttributeMaxDynamicSharedMemorySize, DSMEM_BYTES);
    cudaFuncSetAttribute(attn_mma,   cudaFuncAttributeMaxDynamicSharedMemorySize, DSMEM_BYTES);
    cudaFuncSetAttribute(linear_mma, cudaFuncAttributeMaxDynamicSharedMemorySize, DSMEM_BYTES);
    cudaFuncSetAttribute(sinkhorn_fused, cudaFuncAttributeMaxDynamicSharedMemorySize, SINK_BYTES);

    xsplit_kernel<<<dim3(IN_SIZE / 64, IN_DIM / 64, BATCH), 256>>>(x);
    lwsplit_kernel<<<(OUT_DIM * HID / 4) / 256, 256>>>(lw);
    gemm_k_mma<<<dim3(IN_SIZE / 128, NMAT), 256, DSMEM_BYTES>>>(x, W);
    sinkhorn_fused<<<NMAT * CLU, 512, SINK_BYTES>>>(mask);
    attn_mma<<<dim3(IN_DIM / 128, NMAT), 256, DSMEM_BYTES>>>();
    linear_mma<<<dim3(BATCH * OUT_SIZE / 128, OUT_DIM / 64), 256, DSMEM_BYTES>>>(lb, out);
}

// round 13
// speedup vs baseline: 1.1098x; 1.0385x over previous
#include <cuda_runtime.h>
#include <cuda_bf16.h>
#include <math.h>
#include <stdint.h>

#define BATCH    64
#define IN_SIZE  1024
#define IN_DIM   256
#define HEADS    4
#define OUT_SIZE 64
#define OUT_DIM  256
#define NMAT     (BATCH * HEADS)     /* 256 */
#define HID      (HEADS * IN_DIM)    /* 1024 */
#define MAX_ITER 10

// ---------------------------------------------------------------------------
// Scratch
// ---------------------------------------------------------------------------
__device__ float g_K[(size_t)NMAT * IN_SIZE * OUT_SIZE];        // 64 MB [n][s][o]
__device__ float g_v[(size_t)NMAT * OUT_SIZE];
__device__ __nv_bfloat16 g_x_hi[(size_t)BATCH * IN_SIZE * IN_DIM];    // [b][s][d]
__device__ __nv_bfloat16 g_x_lo[(size_t)BATCH * IN_SIZE * IN_DIM];
__device__ __nv_bfloat16 g_xT_hi[(size_t)BATCH * IN_DIM * IN_SIZE];   // [b][d][s]
__device__ __nv_bfloat16 g_xT_lo[(size_t)BATCH * IN_DIM * IN_SIZE];
__device__ __nv_bfloat16 g_kT_hi[(size_t)NMAT * OUT_SIZE * IN_SIZE];  // [n][o][s]
__device__ __nv_bfloat16 g_kT_lo[(size_t)NMAT * OUT_SIZE * IN_SIZE];
__device__ __nv_bfloat16 g_att_hi[(size_t)BATCH * OUT_SIZE * HID];    // [m][k]
__device__ __nv_bfloat16 g_att_lo[(size_t)BATCH * OUT_SIZE * HID];
__device__ __nv_bfloat16 g_lw_hi[(size_t)OUT_DIM * HID];              // [nn][k]
__device__ __nv_bfloat16 g_lw_lo[(size_t)OUT_DIM * HID];
__device__ __nv_bfloat16 g_w_hi[(size_t)HEADS * OUT_SIZE * IN_DIM];   // [ho][d]
__device__ __nv_bfloat16 g_w_lo[(size_t)HEADS * OUT_SIZE * IN_DIM];

// ---------------------------------------------------------------------------
// Helpers (base-target PTX only)
// ---------------------------------------------------------------------------
__device__ __forceinline__ uint32_t smem_u32(const void* p) {
    uint32_t a;
    asm("{ .reg .u64 t; cvta.to.shared.u64 t, %1; cvt.u32.u64 %0, t; }" : "=r"(a) : "l"(p));
    return a;
}
__device__ __forceinline__ void ldsm4(uint32_t* r, uint32_t a) {
    asm volatile("ldmatrix.sync.aligned.m8n8.x4.shared.b16 {%0,%1,%2,%3}, [%4];"
        : "=r"(r[0]), "=r"(r[1]), "=r"(r[2]), "=r"(r[3]) : "r"(a));
}
__device__ __forceinline__ void ldsm2(uint32_t* r, uint32_t a) {
    asm volatile("ldmatrix.sync.aligned.m8n8.x2.shared.b16 {%0,%1}, [%2];"
        : "=r"(r[0]), "=r"(r[1]) : "r"(a));
}
__device__ __forceinline__ void mma16816(float* c, const uint32_t* a, const uint32_t* b) {
    asm volatile(
        "mma.sync.aligned.m16n8k16.row.col.f32.bf16.bf16.f32 "
        "{%0,%1,%2,%3}, {%4,%5,%6,%7}, {%8,%9}, {%0,%1,%2,%3};"
        : "+f"(c[0]), "+f"(c[1]), "+f"(c[2]), "+f"(c[3])
        : "r"(a[0]), "r"(a[1]), "r"(a[2]), "r"(a[3]), "r"(b[0]), "r"(b[1]));
}
__device__ __forceinline__ uint32_t pack2(__nv_bfloat16 a, __nv_bfloat16 b) {
    uint16_t ua = *(uint16_t*)&a, ub = *(uint16_t*)&b;
    return (uint32_t)ua | ((uint32_t)ub << 16);
}
__device__ __forceinline__ void split2(float f, __nv_bfloat16& h, __nv_bfloat16& l) {
    h = __float2bfloat16(f);
    l = __float2bfloat16(f - __bfloat162float(h));
}
#define CP16(smem, gptr) asm volatile("cp.async.cg.shared.global [%0], [%1], 16;" \
    :: "r"(smem), "l"(gptr) : "memory")
#define CP_COMMIT() asm volatile("cp.async.commit_group;" ::: "memory")
#define CP_WAIT(n)  asm volatile("cp.async.wait_group %0;" :: "n"(n) : "memory")

// Padded bf16 SMEM tiles: row stride 72 elems (144 B).
#define RS 72
// Per-stage layout (pipelined kernels): Ah | Al | Bh | Bl
#define ST_AH 0
#define ST_AL (128 * RS * 2)                  /* 18432 */
#define ST_BH (2 * 128 * RS * 2)              /* 36864 */
#define ST_BL (2 * 128 * RS * 2 + 64 * RS * 2)/* 46080 */
#define ST_BYTES (2 * 128 * RS * 2 + 2 * 64 * RS * 2)  /* 55296 */
#define PIPE_BYTES (2 * ST_BYTES)                      /* 110592 */

// linear_mma (non-pipelined) reuses stage-0 layout
#define DSMEM_BYTES ST_BYTES

// Sinkhorn: 4-CTA cluster, 256 rows per CTA, stride-67 padded K.
#define KST 67
#define SROWS 256
#define SINK_BYTES (SROWS * KST * 4)   /* 68608 */
#define CLU 4

// ---------------------------------------------------------------------------
// Shared loader for pipelined kernels: A 128x64, B 64x64 bf16 hi/lo tiles.
// 256 threads; pure 16B cp.async copies.
// ---------------------------------------------------------------------------
__device__ __forceinline__ void load_tiles_async(
    uint32_t stage_base,
    const __nv_bfloat16* __restrict__ Ahg, const __nv_bfloat16* __restrict__ Alg,
    size_t a_stride,
    const __nv_bfloat16* __restrict__ Bhg, const __nv_bfloat16* __restrict__ Blg,
    size_t b_stride, int col0, int tid)
{
    #pragma unroll
    for (int i = 0; i < 4; ++i) {
        int vi = i * 256 + tid;
        int row = vi >> 3, cu = vi & 7;
        size_t g = (size_t)row * a_stride + col0 + cu * 8;
        uint32_t s = stage_base + (uint32_t)(row * RS + cu * 8) * 2;
        CP16(s, Ahg + g);
        CP16(s + ST_AL, Alg + g);
    }
    #pragma unroll
    for (int i = 0; i < 2; ++i) {
        int vi = i * 256 + tid;
        int row = vi >> 3, cu = vi & 7;
        size_t g = (size_t)row * b_stride + col0 + cu * 8;
        uint32_t s = stage_base + ST_BH + (uint32_t)(row * RS + cu * 8) * 2;
        CP16(s, Bhg + g);
        CP16(s + (ST_BL - ST_BH), Blg + g);
    }
}

// ---------------------------------------------------------------------------
// Kernel 0a/0b: W and lin_w fp32 -> bf16 hi/lo
// ---------------------------------------------------------------------------
__global__ __launch_bounds__(256) void wsplit_kernel(const float* __restrict__ W) {
    int i = blockIdx.x * 256 + threadIdx.x;
    float4 v = *(const float4*)(W + (size_t)i * 4);
    __nv_bfloat16 h0, h1, h2, h3, l0, l1, l2, l3;
    split2(v.x, h0, l0); split2(v.y, h1, l1);
    split2(v.z, h2, l2); split2(v.w, h3, l3);
    *(uint2*)(g_w_hi + (size_t)i * 4) = make_uint2(pack2(h0, h1), pack2(h2, h3));
    *(uint2*)(g_w_lo + (size_t)i * 4) = make_uint2(pack2(l0, l1), pack2(l2, l3));
}
__global__ __launch_bounds__(256) void lwsplit_kernel(const float* __restrict__ lw) {
    int i = blockIdx.x * 256 + threadIdx.x;
    float4 v = *(const float4*)(lw + (size_t)i * 4);
    __nv_bfloat16 h0, h1, h2, h3, l0, l1, l2, l3;
    split2(v.x, h0, l0); split2(v.y, h1, l1);
    split2(v.z, h2, l2); split2(v.w, h3, l3);
    *(uint2*)(g_lw_hi + (size_t)i * 4) = make_uint2(pack2(h0, h1), pack2(h2, h3));
    *(uint2*)(g_lw_lo + (size_t)i * 4) = make_uint2(pack2(l0, l1), pack2(l2, l3));
}

// ---------------------------------------------------------------------------
// Kernel 1: xsplit — emits BOTH row-major g_x_hi/lo[b][s][d] and transposed
// g_xT_hi/lo[b][d][s].
// ---------------------------------------------------------------------------
__global__ __launch_bounds__(256) void xsplit_kernel(const float* __restrict__ x) {
    __shared__ float sm[64][65];
    int tid = threadIdx.x;
    int s0 = blockIdx.x * 64, d0 = blockIdx.y * 64, b = blockIdx.z;
    const float* xb = x + ((size_t)b * IN_SIZE + s0) * IN_DIM + d0;
    #pragma unroll
    for (int i = 0; i < 4; ++i) {
        int vi = i * 256 + tid;
        int rs = vi >> 4, c4 = (vi & 15) * 4;
        float4 v = *(const float4*)(xb + (size_t)rs * IN_DIM + c4);
        sm[rs][c4] = v.x; sm[rs][c4 + 1] = v.y; sm[rs][c4 + 2] = v.z; sm[rs][c4 + 3] = v.w;
        // row-major split output
        __nv_bfloat16 h0, h1, h2, h3, l0, l1, l2, l3;
        split2(v.x, h0, l0); split2(v.y, h1, l1);
        split2(v.z, h2, l2); split2(v.w, h3, l3);
        size_t off = ((size_t)b * IN_SIZE + s0 + rs) * IN_DIM + d0 + c4;
        *(uint2*)(g_x_hi + off) = make_uint2(pack2(h0, h1), pack2(h2, h3));
        *(uint2*)(g_x_lo + off) = make_uint2(pack2(l0, l1), pack2(l2, l3));
    }
    __syncthreads();
    #pragma unroll
    for (int i = 0; i < 4; ++i) {
        int vi = i * 256 + tid;
        int rd = vi >> 4, s4 = (vi & 15) * 4;
        __nv_bfloat16 h[4], l[4];
        #pragma unroll
        for (int j = 0; j < 4; ++j) split2(sm[s4 + j][rd], h[j], l[j]);
        size_t off = ((size_t)b * IN_DIM + d0 + rd) * IN_SIZE + s0 + s4;
        *(uint2*)(g_xT_hi + off) = make_uint2(pack2(h[0], h[1]), pack2(h[2], h[3]));
        *(uint2*)(g_xT_lo + off) = make_uint2(pack2(l[0], l[1]), pack2(l[2], l[3]));
    }
}

// ---------------------------------------------------------------------------
// Shared MMA body for the pipelined kernels (stage-relative bases).
// ---------------------------------------------------------------------------
__device__ __forceinline__ void mma_stage(float c[2][4][4],
                                          uint32_t aBaseH, uint32_t bBaseH) {
    #pragma unroll
    for (int ks = 0; ks < 4; ++ks) {
        uint32_t ah[2][4], al[2][4], bh[4][2], bl[4][2];
        #pragma unroll
        for (int f = 0; f < 2; ++f) {
            uint32_t o = (uint32_t)(f * 16 * RS + ks * 16) * 2;
            ldsm4(ah[f], aBaseH + o);
            ldsm4(al[f], aBaseH + ST_AL + o);
        }
        #pragma unroll
        for (int g = 0; g < 4; ++g) {
            uint32_t o = (uint32_t)(g * 8 * RS + ks * 16) * 2;
            ldsm2(bh[g], bBaseH + o);
            ldsm2(bl[g], bBaseH + (ST_BL - ST_BH) + o);
        }
        #pragma unroll
        for (int f = 0; f < 2; ++f)
            #pragma unroll
            for (int g = 0; g < 4; ++g) {
                mma16816(c[f][g], ah[f], bh[g]);
                mma16816(c[f][g], ah[f], bl[g]);
                mma16816(c[f][g], al[f], bh[g]);
            }
    }
}

// ---------------------------------------------------------------------------
// Kernel 2: K = exp(10 * x·Wᵀ), pipelined cp.async, pre-split inputs.
// CTA = (s-tile 128, n). M=128(s) N=64(o) K=256(d) in 4 chunks.
// ---------------------------------------------------------------------------
__global__ __launch_bounds__(256) void gemm_k_mma(const float* __restrict__) {
    extern __shared__ char dyn[];
    uint32_t base = smem_u32(dyn);

    int tid = threadIdx.x, lane = tid & 31, wid = tid >> 5;
    int wm = wid & 3, wn = wid >> 2;
    int n = blockIdx.y, b = n >> 2, h = n & 3;
    int s0 = blockIdx.x * 128;

    const __nv_bfloat16* Ahg = g_x_hi + ((size_t)b * IN_SIZE + s0) * IN_DIM;
    const __nv_bfloat16* Alg = g_x_lo + ((size_t)b * IN_SIZE + s0) * IN_DIM;
    const __nv_bfloat16* Bhg = g_w_hi + (size_t)h * OUT_SIZE * IN_DIM;
    const __nv_bfloat16* Blg = g_w_lo + (size_t)h * OUT_SIZE * IN_DIM;

    uint32_t aOff = ((wm * 32 + (lane & 15)) * RS + (lane >> 4) * 8) * 2;
    uint32_t bOff = (uint32_t)ST_BH + ((wn * 32 + (lane & 7)) * RS + ((lane >> 3) & 1) * 8) * 2;

    float c[2][4][4];
    #pragma unroll
    for (int f = 0; f < 2; ++f)
        #pragma unroll
        for (int g = 0; g < 4; ++g)
            #pragma unroll
            for (int q = 0; q < 4; ++q) c[f][g][q] = 0.f;

    load_tiles_async(base, Ahg, Alg, IN_DIM, Bhg, Blg, IN_DIM, 0, tid);
    CP_COMMIT();
    for (int ch = 0; ch < 4; ++ch) {
        if (ch + 1 < 4) {
            load_tiles_async(base + ((ch + 1) & 1) * ST_BYTES,
                             Ahg, Alg, IN_DIM, Bhg, Blg, IN_DIM, (ch + 1) * 64, tid);
            CP_COMMIT();
            CP_WAIT(1);
        } else {
            CP_WAIT(0);
        }
        __syncthreads();
        uint32_t st = (uint32_t)(ch & 1) * ST_BYTES;
        mma_stage(c, base + st + aOff, base + st + bOff);
        __syncthreads();
    }

    #pragma unroll
    for (int f = 0; f < 2; ++f) {
        int r0 = s0 + wm * 32 + f * 16 + (lane >> 2);
        #pragma unroll
        for (int g = 0; g < 4; ++g) {
            int o = wn * 32 + g * 8 + (lane & 3) * 2;
            float* p0 = g_K + ((size_t)n * IN_SIZE + r0) * OUT_SIZE + o;
            float* p1 = p0 + 8 * OUT_SIZE;
            *(float2*)p0 = make_float2(expf(c[f][g][0] * 10.f), expf(c[f][g][1] * 10.f));
            *(float2*)p1 = make_float2(expf(c[f][g][2] * 10.f), expf(c[f][g][3] * 10.f));
        }
    }
}

// ---------------------------------------------------------------------------
// Kernel 3: Sinkhorn fused, 4-CTA cluster (R12 known-good, unchanged).
// ---------------------------------------------------------------------------
__global__ void __cluster_dims__(CLU, 1, 1) __launch_bounds__(512, 2)
sinkhorn_fused(const int* __restrict__ mask) {
    extern __shared__ float sK[];
    __shared__ float sm_mask[SROWS];
    __shared__ float sm_v[OUT_SIZE];
    __shared__ float sm_u[SROWS];
    __shared__ float sm_ph[2][SROWS];
    __shared__ float sm_vacc[8][OUT_SIZE];
    __shared__ float sm_exch[2][OUT_SIZE];
    __shared__ float sm_red[16];
    __shared__ float sm_a;

    int tid = threadIdx.x, lane = tid & 31, wid = tid >> 5;
    uint32_t rank;
    asm("mov.u32 %0, %%cluster_ctarank;" : "=r"(rank));
    int n = blockIdx.x >> 2;
    int b = n >> 2;
    int srow0 = (int)rank * SROWS;

    const int* mb = mask + (size_t)b * IN_SIZE;
    float s = ((mb[tid] != 0) ? 1.f : 0.f) + ((mb[tid + 512] != 0) ? 1.f : 0.f);
    #pragma unroll
    for (int off = 16; off; off >>= 1) s += __shfl_xor_sync(0xffffffffu, s, off);
    if (lane == 0) sm_red[wid] = s;
    if (tid < SROWS) sm_mask[tid] = (mb[srow0 + tid] != 0) ? 1.f : 0.f;
    if (tid < OUT_SIZE) sm_v[tid] = 1.0f;
    __syncthreads();
    if (tid == 0) {
        float t = 0.f;
        #pragma unroll
        for (int w = 0; w < 16; ++w) t += sm_red[w];
        sm_a = (float)OUT_SIZE / t;
    }

    {
        const float4* g4 = (const float4*)(g_K + ((size_t)n * IN_SIZE + srow0) * OUT_SIZE);
        #pragma unroll
        for (int i = 0; i < 8; ++i) {
            int idx = i * 512 + tid;
            int row = idx >> 4, q = idx & 15;
            float4 v = g4[idx];
            float* d = sK + row * KST + q * 4;
            d[0] = v.x; d[1] = v.y; d[2] = v.z; d[3] = v.w;
        }
    }
    __syncthreads();
    float a = sm_a;

    int half = tid >> 8;
    int r = tid & 255;
    int o = tid & 63, rg = tid >> 6;

    for (int it = 0; it < MAX_ITER; ++it) {
        {
            const float* kr = sK + r * KST + half * 32;
            const float* vv = sm_v + half * 32;
            float p0 = 0.f, p1 = 0.f;
            #pragma unroll
            for (int j = 0; j < 32; j += 2) {
                p0 = fmaf(kr[j], vv[j], p0);
                p1 = fmaf(kr[j + 1], vv[j + 1], p1);
            }
            sm_ph[half][r] = p0 + p1;
        }
        __syncthreads();
        if (tid < SROWS) {
            float p = sm_ph[0][tid] + sm_ph[1][tid];
            sm_u[tid] = sm_mask[tid] * (a / p);
        }
        __syncthreads();
        {
            const float* kc = sK + (rg * 32) * KST + o;
            const float* uu = sm_u + rg * 32;
            float va = 0.f;
            #pragma unroll
            for (int j = 0; j < 32; ++j) va = fmaf(uu[j], kc[j * KST], va);
            sm_vacc[rg][o] = va;
        }
        __syncthreads();
        float own = 0.f;
        if (tid < OUT_SIZE) {
            #pragma unroll
            for (int w = 0; w < 8; ++w) own += sm_vacc[w][tid];
            sm_exch[it & 1][tid] = own;
        }
        asm volatile("barrier.cluster.arrive.aligned;" ::: "memory");
        asm volatile("barrier.cluster.wait.aligned;" ::: "memory");
        if (tid < OUT_SIZE) {
            uint32_t la = smem_u32(&sm_exch[it & 1][tid]);
            float tot = own;
            #pragma unroll
            for (int pr = 1; pr < CLU; ++pr) {
                uint32_t tr = (rank + pr) & (CLU - 1);
                uint32_t pa;
                asm("mapa.shared::cluster.u32 %0, %1, %2;" : "=r"(pa) : "r"(la), "r"(tr));
                float pv;
                asm volatile("ld.shared::cluster.f32 %0, [%1];" : "=f"(pv) : "r"(pa));
                tot += pv;
            }
            sm_v[tid] = 1.0f / tot;
        }
        __syncthreads();
    }

    if (rank == 0 && tid < OUT_SIZE) g_v[(size_t)n * OUT_SIZE + tid] = sm_v[tid];

    #pragma unroll
    for (int pass = 0; pass < 4; ++pass) {
        int oo = pass * 16 + wid;
        size_t obase = (((size_t)n * OUT_SIZE + oo) * IN_SIZE + srow0) >> 1;
        uint32_t* dh = (uint32_t*)g_kT_hi + obase;
        uint32_t* dl = (uint32_t*)g_kT_lo + obase;
        #pragma unroll
        for (int k = 0; k < 4; ++k) {
            int sr = 64 * k + 2 * lane;
            float w0 = sm_u[sr]     * sK[sr * KST + oo];
            float w1 = sm_u[sr + 1] * sK[(sr + 1) * KST + oo];
            __nv_bfloat16 h0, l0, h1, l1;
            split2(w0, h0, l0); split2(w1, h1, l1);
            dh[32 * k + lane] = pack2(h0, h1);
            dl[32 * k + lane] = pack2(l0, l1);
        }
    }

    asm volatile("barrier.cluster.arrive.aligned;" ::: "memory");
    asm volatile("barrier.cluster.wait.aligned;" ::: "memory");
}

// ---------------------------------------------------------------------------
// Kernel 4: attention, pipelined cp.async: D[d,o] = Σ_s xT[d,s]·(uK)T[o,s].
// ---------------------------------------------------------------------------
__global__ __launch_bounds__(256) void attn_mma() {
    extern __shared__ char dyn[];
    uint32_t base = smem_u32(dyn);
    __shared__ float s_v[OUT_SIZE];

    int tid = threadIdx.x, lane = tid & 31, wid = tid >> 5;
    int wm = wid & 3, wn = wid >> 2;
    int n = blockIdx.y, b = n >> 2, h = n & 3;
    int d0 = blockIdx.x * 128;

    if (tid < OUT_SIZE) s_v[tid] = g_v[(size_t)n * OUT_SIZE + tid];

    const __nv_bfloat16* Ahg = g_xT_hi + ((size_t)b * IN_DIM + d0) * IN_SIZE;
    const __nv_bfloat16* Alg = g_xT_lo + ((size_t)b * IN_DIM + d0) * IN_SIZE;
    const __nv_bfloat16* Bhg = g_kT_hi + (size_t)n * OUT_SIZE * IN_SIZE;
    const __nv_bfloat16* Blg = g_kT_lo + (size_t)n * OUT_SIZE * IN_SIZE;

    uint32_t aOff = ((wm * 32 + (lane & 15)) * RS + (lane >> 4) * 8) * 2;
    uint32_t bOff = (uint32_t)ST_BH + ((wn * 32 + (lane & 7)) * RS + ((lane >> 3) & 1) * 8) * 2;

    float c[2][4][4];
    #pragma unroll
    for (int f = 0; f < 2; ++f)
        #pragma unroll
        for (int g = 0; g < 4; ++g)
            #pragma unroll
            for (int q = 0; q < 4; ++q) c[f][g][q] = 0.f;

    load_tiles_async(base, Ahg, Alg, IN_SIZE, Bhg, Blg, IN_SIZE, 0, tid);
    CP_COMMIT();
    for (int ch = 0; ch < 16; ++ch) {
        if (ch + 1 < 16) {
            load_tiles_async(base + ((ch + 1) & 1) * ST_BYTES,
                             Ahg, Alg, IN_SIZE, Bhg, Blg, IN_SIZE, (ch + 1) * 64, tid);
            CP_COMMIT();
            CP_WAIT(1);
        } else {
            CP_WAIT(0);
        }
        __syncthreads();
        uint32_t st = (uint32_t)(ch & 1) * ST_BYTES;
        mma_stage(c, base + st + aOff, base + st + bOff);
        __syncthreads();
    }

    // Epilogue: v-scale, transpose via SMEM, emit bf16 hi/lo att[m][k]
    float* smF = (float*)dyn;   // 128 x 65 fp32 = 33280 B
    #pragma unroll
    for (int f = 0; f < 2; ++f) {
        int dl = wm * 32 + f * 16 + (lane >> 2);
        #pragma unroll
        for (int g = 0; g < 4; ++g) {
            int o = wn * 32 + g * 8 + (lane & 3) * 2;
            smF[dl * 65 + o]           = s_v[o]     * c[f][g][0];
            smF[dl * 65 + o + 1]       = s_v[o + 1] * c[f][g][1];
            smF[(dl + 8) * 65 + o]     = s_v[o]     * c[f][g][2];
            smF[(dl + 8) * 65 + o + 1] = s_v[o + 1] * c[f][g][3];
        }
    }
    __syncthreads();
    {
        int o = tid >> 2;
        int dseg = (tid & 3) * 32;
        size_t rowbase = ((size_t)b * OUT_SIZE + o) * HID + (size_t)h * IN_DIM + d0 + dseg;
        #pragma unroll
        for (int j = 0; j < 8; ++j) {
            float f0 = smF[(dseg + 4 * j + 0) * 65 + o];
            float f1 = smF[(dseg + 4 * j + 1) * 65 + o];
            float f2 = smF[(dseg + 4 * j + 2) * 65 + o];
            float f3 = smF[(dseg + 4 * j + 3) * 65 + o];
            __nv_bfloat16 h0, h1, h2, h3, l0, l1, l2, l3;
            split2(f0, h0, l0); split2(f1, h1, l1);
            split2(f2, h2, l2); split2(f3, h3, l3);
            *(uint2*)(g_att_hi + rowbase + 4 * j) = make_uint2(pack2(h0, h1), pack2(h2, h3));
            *(uint2*)(g_att_lo + rowbase + 4 * j) = make_uint2(pack2(l0, l1), pack2(l2, l3));
        }
    }
}

// ---------------------------------------------------------------------------
// Kernel 5: out = relu(att @ lin_wᵀ + lin_b), bf16 split-2 HMMA (unchanged).
// ---------------------------------------------------------------------------
__global__ __launch_bounds__(256) void linear_mma(const float* __restrict__ lb,
                                                  float* __restrict__ out) {
    extern __shared__ char dyn[];
    __nv_bfloat16* Ah = (__nv_bfloat16*)(dyn + ST_AH);
    __nv_bfloat16* Al = (__nv_bfloat16*)(dyn + ST_AL);
    __nv_bfloat16* Bh = (__nv_bfloat16*)(dyn + ST_BH);
    __nv_bfloat16* Bl = (__nv_bfloat16*)(dyn + ST_BL);

    int tid = threadIdx.x, lane = tid & 31, wid = tid >> 5;
    int wm = wid & 3, wn = wid >> 2;
    int m0 = blockIdx.x * 128;
    int n0 = blockIdx.y * 64;

    const __nv_bfloat16* ath = g_att_hi + (size_t)m0 * HID;
    const __nv_bfloat16* atl = g_att_lo + (size_t)m0 * HID;
    const __nv_bfloat16* lwh = g_lw_hi + (size_t)n0 * HID;
    const __nv_bfloat16* lwl = g_lw_lo + (size_t)n0 * HID;

    uint32_t aBaseH = smem_u32(Ah) + ((wm * 32 + (lane & 15)) * RS + (lane >> 4) * 8) * 2;
    uint32_t aBaseL = aBaseH + (ST_AL - ST_AH);
    uint32_t bBaseH = smem_u32(Bh) + ((wn * 32 + (lane & 7)) * RS + ((lane >> 3) & 1) * 8) * 2;
    uint32_t bBaseL = bBaseH + (ST_BL - ST_BH);

    float c[2][4][4];
    #pragma unroll
    for (int f = 0; f < 2; ++f)
        #pragma unroll
        for (int g = 0; g < 4; ++g)
            #pragma unroll
            for (int q = 0; q < 4; ++q) c[f][g][q] = 0.f;

    for (int ch = 0; ch < 16; ++ch) {
        int k0 = ch * 64;
        #pragma unroll
        for (int i = 0; i < 4; ++i) {
            int vi = i * 256 + tid;
            int row = vi >> 3, cu = vi & 7;
            size_t goff = (size_t)row * HID + k0 + cu * 8;
            int off = row * RS + cu * 8;
            *(uint4*)(Ah + off) = *(const uint4*)(ath + goff);
            *(uint4*)(Al + off) = *(const uint4*)(atl + goff);
        }
        #pragma unroll
        for (int i = 0; i < 2; ++i) {
            int vi = i * 256 + tid;
            int row = vi >> 3, cu = vi & 7;
            size_t goff = (size_t)row * HID + k0 + cu * 8;
            int off = row * RS + cu * 8;
            *(uint4*)(Bh + off) = *(const uint4*)(lwh + goff);
            *(uint4*)(Bl + off) = *(const uint4*)(lwl + goff);
        }
        __syncthreads();
        #pragma unroll
        for (int ks = 0; ks < 4; ++ks) {
            uint32_t ah[2][4], al[2][4], bh[4][2], bl[4][2];
            #pragma unroll
            for (int f = 0; f < 2; ++f) {
                uint32_t o = (uint32_t)(f * 16 * RS + ks * 16) * 2;
                ldsm4(ah[f], aBaseH + o);
                ldsm4(al[f], aBaseL + o);
            }
            #pragma unroll
            for (int g = 0; g < 4; ++g) {
                uint32_t o = (uint32_t)(g * 8 * RS + ks * 16) * 2;
                ldsm2(bh[g], bBaseH + o);
                ldsm2(bl[g], bBaseL + o);
            }
            #pragma unroll
            for (int f = 0; f < 2; ++f)
                #pragma unroll
                for (int g = 0; g < 4; ++g) {
                    mma16816(c[f][g], ah[f], bh[g]);
                    mma16816(c[f][g], ah[f], bl[g]);
                    mma16816(c[f][g], al[f], bh[g]);
                }
        }
        __syncthreads();
    }

    #pragma unroll
    for (int f = 0; f < 2; ++f) {
        int m = m0 + wm * 32 + f * 16 + (lane >> 2);
        #pragma unroll
        for (int g = 0; g < 4; ++g) {
            int nn = n0 + wn * 32 + g * 8 + (lane & 3) * 2;
            float b0 = lb[nn], b1 = lb[nn + 1];
            float r0 = c[f][g][0] + b0, r1 = c[f][g][1] + b1;
            float r2 = c[f][g][2] + b0, r3 = c[f][g][3] + b1;
            *(float2*)(out + (size_t)m * OUT_DIM + nn) =
                make_float2(r0 > 0.f ? r0 : 0.f, r1 > 0.f ? r1 : 0.f);
            *(float2*)(out + (size_t)(m + 8) * OUT_DIM + nn) =
                make_float2(r2 > 0.f ? r2 : 0.f, r3 > 0.f ? r3 : 0.f);
        }
    }
}

// ---------------------------------------------------------------------------
// Launch
// ---------------------------------------------------------------------------
extern "C" void kernel_launch(void* const* d_in, const int* in_sizes, int n_in,
                              void* d_out, int out_size) {
    const float* x    = (const float*)d_in[0];
    const int*   mask = (const int*)d_in[1];
    const float* W    = (const float*)d_in[2];
    const float* lw   = (const float*)d_in[3];
    const float* lb   = (const float*)d_in[4];
    float*       out  = (float*)d_out;

    cudaFuncSetAttribute(gemm_k_mma, cudaFuncAttributeMaxDynamicSharedMemorySize, PIPE_BYTES);
    cudaFuncSetAttribute(attn_mma,   cudaFuncAttributeMaxDynamicSharedMemorySize, PIPE_BYTES);
    cudaFuncSetAttribute(linear_mma, cudaFuncAttributeMaxDynamicSharedMemorySize, DSMEM_BYTES);
    cudaFuncSetAttribute(sinkhorn_fused, cudaFuncAttributeMaxDynamicSharedMemorySize, SINK_BYTES);

    xsplit_kernel<<<dim3(IN_SIZE / 64, IN_DIM / 64, BATCH), 256>>>(x);
    wsplit_kernel<<<(HEADS * OUT_SIZE * IN_DIM / 4) / 256, 256>>>(W);
    lwsplit_kernel<<<(OUT_DIM * HID / 4) / 256, 256>>>(lw);
    gemm_k_mma<<<dim3(IN_SIZE / 128, NMAT), 256, PIPE_BYTES>>>(x);
    sinkhorn_fused<<<NMAT * CLU, 512, SINK_BYTES>>>(mask);
    attn_mma<<<dim3(IN_DIM / 128, NMAT), 256, PIPE_BYTES>>>();
    linear_mma<<<dim3(BATCH * OUT_SIZE / 128, OUT_DIM / 64), 256, DSMEM_BYTES>>>(lb, out);
}